// round 12
// baseline (speedup 1.0000x reference)
#include <cuda_runtime.h>
#include <cuda_bf16.h>
#include <cstdint>

// Problem constants (fixed by the reference)
#define NB 32      // batch
#define NZ 4000    // nodes
#define NIN 32     // in features
#define NH 64      // hidden
#define NE 64000   // edges

#define NY  (NB * NZ * NIN / 4)   // 1,024,000 float4 loads of x
#define NYB (NY / 512)            // 2000 ydot blocks (512 float4 per block)
#define NEB (NE / 512)            // 125 histogram blocks (512 edges per block)
#define NSCAT ((NE * 8) / 256)    // 2000 scatter blocks
#define NEPI  (NZ / 32)           // 125 epilogue blocks

// Scratch (device globals; zero-initialized at module load; the epilogue
// re-zeroes g_acc / g_deg / counters after use so every execution is clean).
__device__ __align__(16) float g_w[NZ * NB];    // w[z*NB+b] = dinv_z * (x[b,z,:].v)
__device__ __align__(16) float g_acc[NZ * NB];  // acc[z][b] = sum_{s->z} w[s][b]
__device__ int g_deg[NZ];                       // in-degree EXCLUDING self-loop
__device__ __align__(16) float g_v[NIN];        // W @ fc_W
__device__ float g_const;                       // bias . fc_W + fc_b
__device__ unsigned g_done;                     // scatter blocks completed
__device__ unsigned g_epi;                      // epilogue blocks completed

// ---------------------------------------------------------------------------
// K1: degree histogram (blocks 0..NEB-1, 2 edges/thread) + v/const (block NEB).
// g_deg starts at 0 (zero-init on first call, reset by the epilogue after).
// ---------------------------------------------------------------------------
__global__ void k_hist_v(const int* __restrict__ dst,
                         const float* __restrict__ W,
                         const float* __restrict__ bias,
                         const float* __restrict__ fcW,
                         const float* __restrict__ fcb) {
    const int tx = threadIdx.x;
    if (blockIdx.x < NEB) {
        int e = blockIdx.x * 512 + tx;
        int d0 = __ldg(&dst[e]);
        int d1 = __ldg(&dst[e + 256]);
        atomicAdd(&g_deg[d0], 1);
        atomicAdd(&g_deg[d1], 1);
    } else {
        // v[i] = sum_h W[i*NH+h]*fcW[h]; thread (i = tx>>3, j = tx&7)
        int i = tx >> 3;
        int j = tx & 7;
        float p = 0.f;
        #pragma unroll
        for (int k = 0; k < 8; ++k)
            p += W[i * NH + j * 8 + k] * fcW[j * 8 + k];
        p += __shfl_xor_sync(0xFFFFFFFFu, p, 1);
        p += __shfl_xor_sync(0xFFFFFFFFu, p, 2);
        p += __shfl_xor_sync(0xFFFFFFFFu, p, 4);
        if (j == 0) g_v[i] = p;
        if (tx == 0) {
            float s = fcb[0];
            #pragma unroll
            for (int h = 0; h < NH; ++h) s += bias[h] * fcW[h];
            g_const = s;
        }
    }
}

// ---------------------------------------------------------------------------
// K2: streaming ydot, 2 float4 per thread (2x MLP). Thread handles float4
// indices t and t+256 of x (both coalesced); lanes 8k..8k+7 cover one (b,z)
// row; 3-step xor-shuffle reduce per value; leader applies
// dinv_z = rsqrt(deg[z]+1) (deg final) and stores w = dinv_z * y.
// ---------------------------------------------------------------------------
__global__ void k_ydot(const float* __restrict__ x) {
    const int tx = threadIdx.x;
    int t0 = blockIdx.x * 512 + tx;                      // < NY
    int t1 = t0 + 256;
    const float4* xp = reinterpret_cast<const float4*>(x);
    float4 a0 = __ldcs(&xp[t0]);                         // 2 independent loads
    float4 a1 = __ldcs(&xp[t1]);
    float4 vv = reinterpret_cast<const float4*>(g_v)[tx & 7];

    float p0 = a0.x * vv.x + a0.y * vv.y + a0.z * vv.z + a0.w * vv.w;
    float p1 = a1.x * vv.x + a1.y * vv.y + a1.z * vv.z + a1.w * vv.w;
    p0 += __shfl_xor_sync(0xFFFFFFFFu, p0, 1);
    p1 += __shfl_xor_sync(0xFFFFFFFFu, p1, 1);
    p0 += __shfl_xor_sync(0xFFFFFFFFu, p0, 2);
    p1 += __shfl_xor_sync(0xFFFFFFFFu, p1, 2);
    p0 += __shfl_xor_sync(0xFFFFFFFFu, p0, 4);
    p1 += __shfl_xor_sync(0xFFFFFFFFu, p1, 4);

    if ((tx & 7) == 0) {
        int f0 = t0 >> 3;           // row index = b*NZ + z
        int b0 = f0 / NZ;
        int z0 = f0 - b0 * NZ;
        int f1 = t1 >> 3;
        int b1 = f1 / NZ;
        int z1 = f1 - b1 * NZ;
        float d0 = rsqrtf((float)(g_deg[z0] + 1));
        float d1 = rsqrtf((float)(g_deg[z1] + 1));
        g_w[z0 * NB + b0] = p0 * d0;
        g_w[z1 * NB + b1] = p1 * d1;
    }
}

// ---------------------------------------------------------------------------
// K3: scatter + fused epilogue.
// Blocks [0, NSCAT): acc4[d*8+q] += w4[s*8+q], 8 threads/edge, float4 REDs;
//   then fence + one arrival on g_done.
// Blocks [NSCAT, NSCAT+NEPI): epilogue for a 32-z tile. Prefetch w4/deg/dinv
//   (final since K1/K2) BEFORE spinning on g_done so their latency hides
//   under the scatter; after release, read acc, form
//   out[b][z] = dinv_z*(acc+w) + const via a 32x33 tile, self-clean acc/deg,
//   and the last epilogue block resets the counters for the next replay.
// ---------------------------------------------------------------------------
__global__ void k_scatter_out(const int* __restrict__ src,
                              const int* __restrict__ dst,
                              float* __restrict__ out) {
    const int tx = threadIdx.x;

    if (blockIdx.x < NSCAT) {
        int t = blockIdx.x * 256 + tx;            // t = e*8 + q
        int e = t >> 3;
        int q = t & 7;
        int s = __ldg(&src[e]);
        int d = __ldg(&dst[e]);
        float4 m = reinterpret_cast<const float4*>(g_w)[s * 8 + q];
        atomicAdd(&reinterpret_cast<float4*>(g_acc)[d * 8 + q], m);
        __threadfence();                          // order REDs before arrival
        __syncthreads();
        if (tx == 0) atomicAdd(&g_done, 1u);
        return;
    }

    // ---------------- epilogue block ----------------
    __shared__ float tile[32][33];
    const int zb = (blockIdx.x - NSCAT) * 32;     // 4000 = 125*32

    // prefetch (w, deg are final before this kernel launches)
    int zi = tx >> 3;
    int q  = tx & 7;
    int z  = zb + zi;
    int ridx = z * 8 + q;                         // float4 index into acc/w rows
    float4 w4 = reinterpret_cast<const float4*>(g_w)[ridx];
    float dinv = rsqrtf((float)(g_deg[z] + 1));
    float c = g_const;

    // wait for all scatter blocks
    if (tx == 0) {
        while (atomicAdd(&g_done, 0u) < (unsigned)NSCAT) __nanosleep(64);
    }
    __syncthreads();
    __threadfence();                              // acquire: REDs visible

    float4 a4 = reinterpret_cast<const float4*>(g_acc)[ridx];
    tile[zi][q * 4 + 0] = dinv * (a4.x + w4.x);
    tile[zi][q * 4 + 1] = dinv * (a4.y + w4.y);
    tile[zi][q * 4 + 2] = dinv * (a4.z + w4.z);
    tile[zi][q * 4 + 3] = dinv * (a4.w + w4.w);
    __syncthreads();

    // self-clean (all reads of acc/deg happened before the sync)
    reinterpret_cast<float4*>(g_acc)[ridx] = make_float4(0.f, 0.f, 0.f, 0.f);
    if (tx < 32) g_deg[zb + tx] = 0;

    // write side: thread (b = tx>>3, zq = tx&7) writes out[b][zb+4zq .. +3]
    int b  = tx >> 3;
    int zq = tx & 7;
    float4 o;
    o.x = tile[zq * 4 + 0][b] + c;
    o.y = tile[zq * 4 + 1][b] + c;
    o.z = tile[zq * 4 + 2][b] + c;
    o.w = tile[zq * 4 + 3][b] + c;
    reinterpret_cast<float4*>(out)[((size_t)b * NZ + zb) / 4 + zq] = o;

    // last epilogue block resets the handshake counters for the next replay
    __syncthreads();
    if (tx == 0) {
        unsigned n = atomicAdd(&g_epi, 1u);
        if (n == (unsigned)(NEPI - 1)) {
            g_done = 0u;
            g_epi  = 0u;
            __threadfence();
        }
    }
}

// ---------------------------------------------------------------------------
extern "C" void kernel_launch(void* const* d_in, const int* in_sizes, int n_in,
                              void* d_out, int out_size) {
    const float* x    = (const float*)d_in[0];   // [32,4000,32]
    const int*   ei   = (const int*)  d_in[1];   // [2,64000]
    const float* W    = (const float*)d_in[2];   // [32,64]
    const float* bias = (const float*)d_in[3];   // [64]
    const float* fcW  = (const float*)d_in[4];   // [64]
    const float* fcb  = (const float*)d_in[5];   // [1]
    float* out = (float*)d_out;                  // [32,4000]

    const int* src = ei;
    const int* dst = ei + NE;

    k_hist_v<<<NEB + 1, 256>>>(dst, W, bias, fcW, fcb);
    k_ydot<<<NYB, 256>>>(x);
    k_scatter_out<<<NSCAT + NEPI, 256>>>(src, dst, out);
}

// round 13
// speedup vs baseline: 1.2759x; 1.2759x over previous
#include <cuda_runtime.h>
#include <cuda_bf16.h>
#include <cstdint>

// Problem constants (fixed by the reference)
#define NB 32      // batch
#define NZ 4000    // nodes
#define NIN 32     // in features
#define NH 64      // hidden
#define NE 64000   // edges

#define NY  (NB * NZ * NIN / 4)   // 1,024,000 float4 loads of x
#define NYB (NY / 1024)           // 1000 ydot blocks (1024 float4 per block)
#define NEB (NE / 256)            // 250 histogram blocks
#define NSB ((NE * 8) / 512)      // 1000 scatter blocks (2 float4 REDs/thread)

// Scratch (device globals; zero-initialized at module load; k_out re-zeroes
// g_acc / g_deg after use so every execution starts clean).
__device__ __align__(16) float g_w[NZ * NB];    // w[z*NB+b] = dinv_z * (x[b,z,:].v)
__device__ __align__(16) float g_acc[NZ * NB];  // acc[z][b] = sum_{s->z} w[s][b]
__device__ int g_deg[NZ];                       // in-degree EXCLUDING self-loop
__device__ __align__(16) float g_v[NIN];        // W @ fc_W
__device__ float g_const;                       // bias . fc_W + fc_b

// ---------------------------------------------------------------------------
// K1: degree histogram (blocks 0..NEB-1, 1 edge/thread) + v/const (block NEB).
// g_deg starts at 0 (zero-init on first call, reset by k_out afterwards).
// ---------------------------------------------------------------------------
__global__ void k_hist_v(const int* __restrict__ dst,
                         const float* __restrict__ W,
                         const float* __restrict__ bias,
                         const float* __restrict__ fcW,
                         const float* __restrict__ fcb) {
    const int tx = threadIdx.x;
    if (blockIdx.x < NEB) {
        int e = blockIdx.x * 256 + tx;
        atomicAdd(&g_deg[__ldg(&dst[e])], 1);
    } else {
        // v[i] = sum_h W[i*NH+h]*fcW[h]; thread (i = tx>>3, j = tx&7)
        int i = tx >> 3;
        int j = tx & 7;
        float p = 0.f;
        #pragma unroll
        for (int k = 0; k < 8; ++k)
            p += W[i * NH + j * 8 + k] * fcW[j * 8 + k];
        p += __shfl_xor_sync(0xFFFFFFFFu, p, 1);
        p += __shfl_xor_sync(0xFFFFFFFFu, p, 2);
        p += __shfl_xor_sync(0xFFFFFFFFu, p, 4);
        if (j == 0) g_v[i] = p;
        if (tx == 0) {
            float s = fcb[0];
            #pragma unroll
            for (int h = 0; h < NH; ++h) s += bias[h] * fcW[h];
            g_const = s;
        }
    }
}

// ---------------------------------------------------------------------------
// K2: streaming ydot, 4 float4 per thread (4x MLP). Thread handles float4
// indices t, t+256, t+512, t+768 of x (all coalesced); lanes 8k..8k+7 cover
// one (b,z) row; 3-step xor-shuffle reduce per value; leader applies
// dinv_z = rsqrt(deg[z]+1) (deg final) and stores w = dinv_z * y.
// ---------------------------------------------------------------------------
__global__ void k_ydot(const float* __restrict__ x) {
    const int tx = threadIdx.x;
    const int t0 = blockIdx.x * 1024 + tx;               // < NY
    const float4* xp = reinterpret_cast<const float4*>(x);
    // 4 independent loads front-loaded for MLP
    float4 a0 = __ldcs(&xp[t0]);
    float4 a1 = __ldcs(&xp[t0 + 256]);
    float4 a2 = __ldcs(&xp[t0 + 512]);
    float4 a3 = __ldcs(&xp[t0 + 768]);
    float4 vv = reinterpret_cast<const float4*>(g_v)[tx & 7];

    float p0 = a0.x * vv.x + a0.y * vv.y + a0.z * vv.z + a0.w * vv.w;
    float p1 = a1.x * vv.x + a1.y * vv.y + a1.z * vv.z + a1.w * vv.w;
    float p2 = a2.x * vv.x + a2.y * vv.y + a2.z * vv.z + a2.w * vv.w;
    float p3 = a3.x * vv.x + a3.y * vv.y + a3.z * vv.z + a3.w * vv.w;
    #pragma unroll
    for (int o = 1; o <= 4; o <<= 1) {
        p0 += __shfl_xor_sync(0xFFFFFFFFu, p0, o);
        p1 += __shfl_xor_sync(0xFFFFFFFFu, p1, o);
        p2 += __shfl_xor_sync(0xFFFFFFFFu, p2, o);
        p3 += __shfl_xor_sync(0xFFFFFFFFu, p3, o);
    }

    if ((tx & 7) == 0) {
        #pragma unroll
        for (int u = 0; u < 4; ++u) {
            int t = t0 + u * 256;
            float p = (u == 0) ? p0 : (u == 1) ? p1 : (u == 2) ? p2 : p3;
            int f = t >> 3;             // row index = b*NZ + z
            int b = f / NZ;
            int z = f - b * NZ;
            float dinv = rsqrtf((float)(g_deg[z] + 1));
            g_w[z * NB + b] = p * dinv;
        }
    }
}

// ---------------------------------------------------------------------------
// K3: minimal edge scatter: acc4[d*8+q] += w4[s*8+q]. 8 threads per edge,
// 2 independent float4 REDs per thread (fire-and-forget; no fences).
// g_acc starts at 0 (zero-init / reset by k_out).
// ---------------------------------------------------------------------------
__global__ void k_scatter(const int* __restrict__ src,
                          const int* __restrict__ dst) {
    int t0 = blockIdx.x * 512 + threadIdx.x;   // t = e*8 + q
    int t1 = t0 + 256;
    int e0 = t0 >> 3, q0 = t0 & 7;
    int e1 = t1 >> 3, q1 = t1 & 7;
    int s0 = __ldg(&src[e0]);
    int d0 = __ldg(&dst[e0]);
    int s1 = __ldg(&src[e1]);
    int d1 = __ldg(&dst[e1]);
    float4 m0 = reinterpret_cast<const float4*>(g_w)[s0 * 8 + q0];
    float4 m1 = reinterpret_cast<const float4*>(g_w)[s1 * 8 + q1];
    atomicAdd(&reinterpret_cast<float4*>(g_acc)[d0 * 8 + q0], m0);
    atomicAdd(&reinterpret_cast<float4*>(g_acc)[d1 * 8 + q1], m1);
}

// ---------------------------------------------------------------------------
// K4: out[b][z] = dinv_z*(acc[z][b] + w[z][b]) + const  (R11 version, exact).
// 125 blocks x 256 threads, 32x33 tile, float4 everywhere.
// Self-cleans acc and deg for the next graph replay.
// ---------------------------------------------------------------------------
__global__ void k_out(float* __restrict__ out) {
    __shared__ float tile[32][33];
    const int tx = threadIdx.x;
    const int zb = blockIdx.x * 32;           // NZ % 32 == 0 (4000 = 125*32)

    // read side: thread (zi = tx>>3, q = tx&7) handles float4 q of row zb+zi
    int zi = tx >> 3;
    int q  = tx & 7;
    int z  = zb + zi;
    int ridx = z * 8 + q;                     // float4 index into acc/w rows
    float dinv = rsqrtf((float)(g_deg[z] + 1));   // broadcast among 8 threads
    float4 a4 = reinterpret_cast<const float4*>(g_acc)[ridx];
    float4 w4 = reinterpret_cast<const float4*>(g_w)[ridx];
    tile[zi][q * 4 + 0] = dinv * (a4.x + w4.x);
    tile[zi][q * 4 + 1] = dinv * (a4.y + w4.y);
    tile[zi][q * 4 + 2] = dinv * (a4.z + w4.z);
    tile[zi][q * 4 + 3] = dinv * (a4.w + w4.w);
    __syncthreads();

    // self-clean (all reads of acc/deg happened before the sync)
    reinterpret_cast<float4*>(g_acc)[ridx] = make_float4(0.f, 0.f, 0.f, 0.f);
    if (tx < 32) g_deg[zb + tx] = 0;

    // write side: thread (b = tx>>3, zq = tx&7) writes out[b][zb+4zq .. +3]
    int b  = tx >> 3;
    int zq = tx & 7;
    float c = g_const;
    float4 o;
    o.x = tile[zq * 4 + 0][b] + c;
    o.y = tile[zq * 4 + 1][b] + c;
    o.z = tile[zq * 4 + 2][b] + c;
    o.w = tile[zq * 4 + 3][b] + c;
    reinterpret_cast<float4*>(out)[((size_t)b * NZ + zb) / 4 + zq] = o;
}

// ---------------------------------------------------------------------------
extern "C" void kernel_launch(void* const* d_in, const int* in_sizes, int n_in,
                              void* d_out, int out_size) {
    const float* x    = (const float*)d_in[0];   // [32,4000,32]
    const int*   ei   = (const int*)  d_in[1];   // [2,64000]
    const float* W    = (const float*)d_in[2];   // [32,64]
    const float* bias = (const float*)d_in[3];   // [64]
    const float* fcW  = (const float*)d_in[4];   // [64]
    const float* fcb  = (const float*)d_in[5];   // [1]
    float* out = (float*)d_out;                  // [32,4000]

    const int* src = ei;
    const int* dst = ei + NE;

    k_hist_v<<<NEB + 1, 256>>>(dst, W, bias, fcW, fcb);
    k_ydot<<<NYB, 256>>>(x);
    k_scatter<<<NSB, 256>>>(src, dst);
    k_out<<<NZ / 32, 256>>>(out);
}

// round 15
// speedup vs baseline: 1.2814x; 1.0043x over previous
#include <cuda_runtime.h>
#include <cuda_bf16.h>
#include <cstdint>

// Problem constants (fixed by the reference)
#define NB 32      // batch
#define NZ 4000    // nodes
#define NIN 32     // in features
#define NH 64      // hidden
#define NE 64000   // edges

#define NY  (NB * NZ * NIN / 4)   // 1,024,000 float4 loads of x
#define NYB (NY / 1024)           // 1000 ydot blocks (1024 float4 per block)
#define NEB (NE / 256)            // 250 histogram blocks
#define NSB ((NE * 8) / 512)      // 1000 scatter blocks (2 float4 REDs/thread)

// Scratch (device globals; zero-initialized at module load).
// g_acc is fully OVERWRITTEN by k_ydot each execution (self-loop init), so it
// needs no zeroing; g_deg is re-zeroed by k_out after use.
__device__ __align__(16) float g_w[NZ * NB];    // w[z*NB+b] = dinv_z * (x[b,z,:].v)
__device__ __align__(16) float g_acc[NZ * NB];  // acc[z][b]: init w_z, + sum_{s->z} w_s
__device__ int g_deg[NZ];                       // in-degree EXCLUDING self-loop
__device__ __align__(16) float g_v[NIN];        // W @ fc_W
__device__ float g_const;                       // bias . fc_W + fc_b

// ---------------------------------------------------------------------------
// K1: degree histogram (blocks 0..NEB-1, 1 edge/thread) + v/const (block NEB).
// g_deg starts at 0 (zero-init on first call, reset by k_out afterwards).
// ---------------------------------------------------------------------------
__global__ void k_hist_v(const int* __restrict__ dst,
                         const float* __restrict__ W,
                         const float* __restrict__ bias,
                         const float* __restrict__ fcW,
                         const float* __restrict__ fcb) {
    const int tx = threadIdx.x;
    if (blockIdx.x < NEB) {
        int e = blockIdx.x * 256 + tx;
        atomicAdd(&g_deg[__ldg(&dst[e])], 1);
    } else {
        // v[i] = sum_h W[i*NH+h]*fcW[h]; thread (i = tx>>3, j = tx&7)
        int i = tx >> 3;
        int j = tx & 7;
        float p = 0.f;
        #pragma unroll
        for (int k = 0; k < 8; ++k)
            p += W[i * NH + j * 8 + k] * fcW[j * 8 + k];
        p += __shfl_xor_sync(0xFFFFFFFFu, p, 1);
        p += __shfl_xor_sync(0xFFFFFFFFu, p, 2);
        p += __shfl_xor_sync(0xFFFFFFFFu, p, 4);
        if (j == 0) g_v[i] = p;
        if (tx == 0) {
            float s = fcb[0];
            #pragma unroll
            for (int h = 0; h < NH; ++h) s += bias[h] * fcW[h];
            g_const = s;
        }
    }
}

// ---------------------------------------------------------------------------
// K2: streaming ydot, 4 float4 per thread (4x MLP). Thread handles float4
// indices t, t+256, t+512, t+768 of x (all coalesced); lanes 8k..8k+7 cover
// one (b,z) row; 3-step xor-shuffle reduce per value; leader applies
// dinv_z = rsqrt(deg[z]+1) (deg final, K1 done) and stores
//   g_w[z,b]   = w = dinv_z * y       (read by scatter)
//   g_acc[z,b] = w                    (self-loop init; REDs accumulate on top)
// ---------------------------------------------------------------------------
__global__ void k_ydot(const float* __restrict__ x) {
    const int tx = threadIdx.x;
    const int t0 = blockIdx.x * 1024 + tx;               // < NY
    const float4* xp = reinterpret_cast<const float4*>(x);
    // 4 independent loads front-loaded for MLP
    float4 a0 = __ldcs(&xp[t0]);
    float4 a1 = __ldcs(&xp[t0 + 256]);
    float4 a2 = __ldcs(&xp[t0 + 512]);
    float4 a3 = __ldcs(&xp[t0 + 768]);
    float4 vv = reinterpret_cast<const float4*>(g_v)[tx & 7];

    float p0 = a0.x * vv.x + a0.y * vv.y + a0.z * vv.z + a0.w * vv.w;
    float p1 = a1.x * vv.x + a1.y * vv.y + a1.z * vv.z + a1.w * vv.w;
    float p2 = a2.x * vv.x + a2.y * vv.y + a2.z * vv.z + a2.w * vv.w;
    float p3 = a3.x * vv.x + a3.y * vv.y + a3.z * vv.z + a3.w * vv.w;
    #pragma unroll
    for (int o = 1; o <= 4; o <<= 1) {
        p0 += __shfl_xor_sync(0xFFFFFFFFu, p0, o);
        p1 += __shfl_xor_sync(0xFFFFFFFFu, p1, o);
        p2 += __shfl_xor_sync(0xFFFFFFFFu, p2, o);
        p3 += __shfl_xor_sync(0xFFFFFFFFu, p3, o);
    }

    if ((tx & 7) == 0) {
        #pragma unroll
        for (int u = 0; u < 4; ++u) {
            int t = t0 + u * 256;
            float p = (u == 0) ? p0 : (u == 1) ? p1 : (u == 2) ? p2 : p3;
            int f = t >> 3;             // row index = b*NZ + z
            int b = f / NZ;
            int z = f - b * NZ;
            float w = p * rsqrtf((float)(g_deg[z] + 1));
            g_w[z * NB + b]   = w;
            g_acc[z * NB + b] = w;      // self-loop init (overwrites old state)
        }
    }
}

// ---------------------------------------------------------------------------
// K3: minimal edge scatter: acc4[d*8+q] += w4[s*8+q]. 8 threads per edge,
// 2 independent float4 REDs per thread (fire-and-forget; no fences).
// ---------------------------------------------------------------------------
__global__ void k_scatter(const int* __restrict__ src,
                          const int* __restrict__ dst) {
    int t0 = blockIdx.x * 512 + threadIdx.x;   // t = e*8 + q
    int t1 = t0 + 256;
    int e0 = t0 >> 3, q0 = t0 & 7;
    int e1 = t1 >> 3, q1 = t1 & 7;
    int s0 = __ldg(&src[e0]);
    int d0 = __ldg(&dst[e0]);
    int s1 = __ldg(&src[e1]);
    int d1 = __ldg(&dst[e1]);
    float4 m0 = reinterpret_cast<const float4*>(g_w)[s0 * 8 + q0];
    float4 m1 = reinterpret_cast<const float4*>(g_w)[s1 * 8 + q1];
    atomicAdd(&reinterpret_cast<float4*>(g_acc)[d0 * 8 + q0], m0);
    atomicAdd(&reinterpret_cast<float4*>(g_acc)[d1 * 8 + q1], m1);
}

// ---------------------------------------------------------------------------
// K4: out[b][z] = dinv_z * acc[z][b] + const   (acc already holds the
// self-loop term). 125 blocks x 256 threads, 32x33 tile, float4 everywhere.
// Only g_deg needs self-cleaning (acc is overwritten by k_ydot next replay).
// ---------------------------------------------------------------------------
__global__ void k_out(float* __restrict__ out) {
    __shared__ float tile[32][33];
    const int tx = threadIdx.x;
    const int zb = blockIdx.x * 32;           // NZ % 32 == 0 (4000 = 125*32)

    // read side: thread (zi = tx>>3, q = tx&7) handles float4 q of row zb+zi
    int zi = tx >> 3;
    int q  = tx & 7;
    int z  = zb + zi;
    int ridx = z * 8 + q;                     // float4 index into acc rows
    float dinv = rsqrtf((float)(g_deg[z] + 1));   // broadcast among 8 threads
    float4 a4 = reinterpret_cast<const float4*>(g_acc)[ridx];
    tile[zi][q * 4 + 0] = dinv * a4.x;
    tile[zi][q * 4 + 1] = dinv * a4.y;
    tile[zi][q * 4 + 2] = dinv * a4.z;
    tile[zi][q * 4 + 3] = dinv * a4.w;
    __syncthreads();

    // self-clean deg (all reads happened before the sync)
    if (tx < 32) g_deg[zb + tx] = 0;

    // write side: thread (b = tx>>3, zq = tx&7) writes out[b][zb+4zq .. +3]
    int b  = tx >> 3;
    int zq = tx & 7;
    float c = g_const;
    float4 o;
    o.x = tile[zq * 4 + 0][b] + c;
    o.y = tile[zq * 4 + 1][b] + c;
    o.z = tile[zq * 4 + 2][b] + c;
    o.w = tile[zq * 4 + 3][b] + c;
    reinterpret_cast<float4*>(out)[((size_t)b * NZ + zb) / 4 + zq] = o;
}

// ---------------------------------------------------------------------------
extern "C" void kernel_launch(void* const* d_in, const int* in_sizes, int n_in,
                              void* d_out, int out_size) {
    const float* x    = (const float*)d_in[0];   // [32,4000,32]
    const int*   ei   = (const int*)  d_in[1];   // [2,64000]
    const float* W    = (const float*)d_in[2];   // [32,64]
    const float* bias = (const float*)d_in[3];   // [64]
    const float* fcW  = (const float*)d_in[4];   // [64]
    const float* fcb  = (const float*)d_in[5];   // [1]
    float* out = (float*)d_out;                  // [32,4000]

    const int* src = ei;
    const int* dst = ei + NE;

    k_hist_v<<<NEB + 1, 256>>>(dst, W, bias, fcW, fcb);
    k_ydot<<<NYB, 256>>>(x);
    k_scatter<<<NSB, 256>>>(src, dst);
    k_out<<<NZ / 32, 256>>>(out);
}